// round 4
// baseline (speedup 1.0000x reference)
#include <cuda_runtime.h>

#define DD 768
#define Q6 6
#define INV_T 14.285714285714286f
#define CSHIFT 14.285714285714286f
#define MAXROWS 8192
#define SEG 4

// ---- persistent device state (zero at module load; k_fin resets after use) ----
static __device__ float g_S[512];
static __device__ float g_pos[512];
static __device__ float g_sonnet_sum;
static __device__ int   g_rowIdx[MAXROWS];
static __device__ int   g_labArr[MAXROWS];
static __device__ float g_rowS[MAXROWS];
static __device__ int   g_nvalid;
static __device__ volatile int g_ready;   // 0 -> 1 by init block; reset by k_fin

__device__ __forceinline__ float wsum(float v) {
    v += __shfl_xor_sync(0xffffffffu, v, 16);
    v += __shfl_xor_sync(0xffffffffu, v, 8);
    v += __shfl_xor_sync(0xffffffffu, v, 4);
    v += __shfl_xor_sync(0xffffffffu, v, 2);
    v += __shfl_xor_sync(0xffffffffu, v, 1);
    return v;
}

// per-lane 24 floats of a 768-float row, coalesced float4 pattern
__device__ __forceinline__ float load_chunk(const float* __restrict__ row, float* v, int lane) {
    const float4* r4 = (const float4*)row;
    float sq = 0.f;
#pragma unroll
    for (int q = 0; q < Q6; ++q) {
        float4 t = r4[lane + 32 * q];
        v[4*q+0] = t.x; v[4*q+1] = t.y; v[4*q+2] = t.z; v[4*q+3] = t.w;
        sq = fmaf(t.x, t.x, sq); sq = fmaf(t.y, t.y, sq);
        sq = fmaf(t.z, t.z, sq); sq = fmaf(t.w, t.w, sq);
    }
    return sq;
}

// sum-of-squares only (no register array kept live)
__device__ __forceinline__ float sumsq_row(const float* __restrict__ row, int lane) {
    const float4* r4 = (const float4*)row;
    float sq = 0.f;
#pragma unroll
    for (int q = 0; q < Q6; ++q) {
        float4 t = r4[lane + 32 * q];
        sq = fmaf(t.x, t.x, sq); sq = fmaf(t.y, t.y, sq);
        sq = fmaf(t.z, t.z, sq); sq = fmaf(t.w, t.w, sq);
    }
    return sq;
}

// ---------------- role: init (bid 0): dtype detect + compact valid rows ----------------
__device__ void init_block(const void* __restrict__ labels, int nRows) {
    __shared__ int s_cnt, s_ok;
    int tid = threadIdx.x;
    if (tid == 0) { s_cnt = 0; s_ok = 1; }
    __syncthreads();
    // int64 little-endian: odd int32 words are sign extensions (0 or -1).
    const int2* p2 = (const int2*)labels;
    int half = nRows >> 1;
    bool bad = false;
    for (int i = tid; i < half; i += 256) {
        int hi = p2[i].y;
        if (hi != 0 && hi != -1) bad = true;
    }
    if (bad) s_ok = 0;   // benign race: all writers store 0
    __syncthreads();
    int lab64 = s_ok;
    const int* p = (const int*)labels;
    for (int r = tid; r < nRows; r += 256) {
        int lab = lab64 ? (int)((const long long*)labels)[r] : p[r];
        if (lab >= 0) {
            int slot = atomicAdd(&s_cnt, 1);
            g_rowIdx[slot] = r;
            g_labArr[slot] = lab;
            g_rowS[slot]  = 0.f;
        }
    }
    __threadfence();      // each thread's worklist writes gpu-visible
    __syncthreads();
    if (tid == 0) {
        g_nvalid = s_cnt;
        __threadfence();
        g_ready = 1;      // release
    }
}

// ---------------- role: MLM segment stream ----------------
__device__ void mlm_seg(const float* __restrict__ logits, int V, int stride, int bid) {
    while (g_ready == 0) __nanosleep(100);
    __threadfence();      // acquire
    int nseg  = g_nvalid * SEG;
    int n2    = V >> 1;
    int segf2 = (n2 + SEG - 1) / SEG;
    for (int s = bid; s < nseg; s += stride) {
        int slot = s >> 2, sg = s & 3;
        int row  = g_rowIdx[slot];
        const float2* x2 = (const float2*)(logits + (size_t)row * V);  // 8B aligned always
        int start = sg * segf2;
        int end   = min(n2, start + segf2);
        float a0 = 0.f, a1 = 0.f;
        int i = start + threadIdx.x;
        int endu = end - 256 * 3;
        for (; i < endu; i += 256 * 4) {
            float2 v[4];
#pragma unroll
            for (int u = 0; u < 4; ++u) v[u] = x2[i + 256 * u];
#pragma unroll
            for (int u = 0; u < 4; ++u) { a0 += __expf(v[u].x); a1 += __expf(v[u].y); }
        }
        for (; i < end; i += 256) { float2 v = x2[i]; a0 += __expf(v.x); a1 += __expf(v.y); }
        float w = wsum(a0 + a1);
        if ((threadIdx.x & 31) == 0) atomicAdd(&g_rowS[slot], w);
    }
}

// ------- role: InfoNCE tile (8 anchors x <=64 negatives) -------
__device__ void infonce_block(const float* __restrict__ A,
                              const float* __restrict__ Pp,
                              const float* __restrict__ Ng,
                              int nP, int nN, int ga, int gn, int Sbase) {
    __shared__ float inv_nn[64];
    int tid = threadIdx.x, w = tid >> 5, lane = tid & 31;
    int nBase = gn << 6;
    int nCnt = min(64, nN - nBase);
    for (int j = w; j < nCnt; j += 8) {
        float sq = wsum(sumsq_row(Ng + (size_t)(nBase + j) * DD, lane));
        if (lane == 0) inv_nn[j] = rsqrtf(fmaxf(sq, 1e-24f));
    }
    __syncthreads();
    int a = ga * 8 + w;
    if (a >= nP) return;
    float av[24];
    float sq = wsum(load_chunk(A + (size_t)a * DD, av, lane));
    float inv = rsqrtf(fmaxf(sq, 1e-24f));
#pragma unroll
    for (int i = 0; i < 24; ++i) av[i] *= inv;

    float acc = 0.f;
    for (int j = 0; j < nCnt; ++j) {
        const float4* r4 = (const float4*)(Ng + (size_t)(nBase + j) * DD);
        float d = 0.f;
#pragma unroll
        for (int q = 0; q < Q6; ++q) {
            float4 t = r4[lane + 32 * q];
            d = fmaf(av[4*q+0], t.x, d);
            d = fmaf(av[4*q+1], t.y, d);
            d = fmaf(av[4*q+2], t.z, d);
            d = fmaf(av[4*q+3], t.w, d);
        }
        d = wsum(d);
        acc += __expf(fmaf(d, inv_nn[j] * INV_T, -CSHIFT));  // sim <= 1/T, no max needed
    }
    if (gn == 0) {  // streamed positive (no second register array)
        const float4* r4 = (const float4*)(Pp + (size_t)a * DD);
        float dp = 0.f, psq = 0.f;
#pragma unroll
        for (int q = 0; q < Q6; ++q) {
            float4 t = r4[lane + 32 * q];
            dp = fmaf(av[4*q+0], t.x, dp);
            dp = fmaf(av[4*q+1], t.y, dp);
            dp = fmaf(av[4*q+2], t.z, dp);
            dp = fmaf(av[4*q+3], t.w, dp);
            psq = fmaf(t.x, t.x, psq); psq = fmaf(t.y, t.y, psq);
            psq = fmaf(t.z, t.z, psq); psq = fmaf(t.w, t.w, psq);
        }
        dp = wsum(dp); psq = wsum(psq);
        float pos = dp * rsqrtf(fmaxf(psq, 1e-24f)) * INV_T;
        acc += __expf(pos - CSHIFT);
        if (lane == 0) g_pos[Sbase + a] = pos;
    }
    if (lane == 0) atomicAdd(&g_S[Sbase + a], acc);
}

// ---------------- role: sonnet (single block) ----------------
__device__ void sonnet_block(const float* __restrict__ E, int Bs) {
    __shared__ float invn[32];
    int tid = threadIdx.x, w = tid >> 5, lane = tid & 31;
    for (int i = w; i < Bs; i += 8) {
        float sq = wsum(sumsq_row(E + (size_t)i * DD, lane));
        if (lane == 0) invn[i] = rsqrtf(fmaxf(sq, 1e-24f));
    }
    __syncthreads();
    for (int i = w; i < Bs; i += 8) {
        float xv[24];
        load_chunk(E + (size_t)i * DD, xv, lane);
        float si = invn[i];
        float acc = 0.f, diag = 0.f;
        for (int j = 0; j < Bs; ++j) {
            const float4* r4 = (const float4*)(E + (size_t)j * DD);
            float d = 0.f;
#pragma unroll
            for (int q = 0; q < Q6; ++q) {
                float4 t = r4[lane + 32 * q];
                d = fmaf(xv[4*q+0], t.x, d);
                d = fmaf(xv[4*q+1], t.y, d);
                d = fmaf(xv[4*q+2], t.z, d);
                d = fmaf(xv[4*q+3], t.w, d);
            }
            d = wsum(d);
            float sim = d * si * invn[j] * INV_T;
            acc += __expf(sim - CSHIFT);
            if (j == i) diag = sim;
        }
        if (lane == 0) atomicAdd(&g_sonnet_sum, logf(acc) + CSHIFT - diag);
    }
}

// ---------------- fused main kernel ----------------
// bid 0: init | next LA*LN+QA*QN+1: infonce+sonnet (run during init window) | rest: MLM segs
__global__ void __launch_bounds__(256, 6)
k_main(const float* __restrict__ logits, const void* __restrict__ labels,
       int nRows, int V,
       const float* __restrict__ lA, const float* __restrict__ lP,
       const float* __restrict__ lN, int PL, int NL, int LA, int LN,
       const float* __restrict__ qA, const float* __restrict__ qP,
       const float* __restrict__ qN, int PQ, int NQ, int QA, int QN,
       const float* __restrict__ sE, int Bs) {
    int b = blockIdx.x;
    if (b == 0) { init_block(labels, nRows); return; }
    b -= 1;
    if (b < LA * LN) { infonce_block(lA, lP, lN, PL, NL, b / LN, b % LN, 0); return; }
    b -= LA * LN;
    if (b < QA * QN) { infonce_block(qA, qP, qN, PQ, NQ, b / QN, b % QN, PL); return; }
    b -= QA * QN;
    if (b == 0) { sonnet_block(sE, Bs); return; }
    b -= 1;
    mlm_seg(logits, V, nRows, b);
}

// ---------------- finalize + state reset ----------------
__global__ void k_fin(const float* __restrict__ logits, int V,
                      float* __restrict__ out, int PL, int PQ,
                      float invPL, float invPQ, int Bs) {
    __shared__ float red[512];
    int tid = threadIdx.x;
    int nv = g_nvalid;
    float invNv = 1.0f / (float)max(nv, 1);
    float acc = 0.f;
    for (int i = tid; i < nv; i += 512) {
        float xl = logits[(size_t)g_rowIdx[i] * V + g_labArr[i]];
        acc += logf(g_rowS[i]) - xl;
    }
    acc *= 0.5f * invNv;
    for (int i = tid; i < PL + PQ; i += 512) {
        float wgt = (i < PL) ? (0.2f * invPL) : (0.2f * invPQ);
        acc += wgt * (logf(g_S[i]) + CSHIFT - g_pos[i]);
    }
    red[tid] = acc;
    __syncthreads();
    for (int s = 256; s; s >>= 1) {
        if (tid < s) red[tid] += red[tid + s];
        __syncthreads();
    }
    if (tid == 0)
        out[0] = red[0] + 0.1f * g_sonnet_sum / (float)Bs;
    __syncthreads();
    // reset state for the next graph replay (reads above are complete)
    for (int i = tid; i < 512; i += 512) { g_S[i] = 0.f; g_pos[i] = 0.f; }
    if (tid == 0) { g_sonnet_sum = 0.f; g_ready = 0; }
}

extern "C" void kernel_launch(void* const* d_in, const int* in_sizes, int n_in,
                              void* d_out, int out_size) {
    const float* logits = (const float*)d_in[0];
    const void*  labels = d_in[1];
    const float* lA = (const float*)d_in[2];
    const float* lP = (const float*)d_in[3];
    const float* lN = (const float*)d_in[4];
    const float* qA = (const float*)d_in[5];
    const float* qP = (const float*)d_in[6];
    const float* qN = (const float*)d_in[7];
    const float* sE = (const float*)d_in[8];

    int nRows = in_sizes[1];
    int V  = in_sizes[0] / nRows;
    int PL = in_sizes[2] / DD, NL = in_sizes[4] / DD;
    int PQ = in_sizes[5] / DD, NQ = in_sizes[7] / DD;
    int Bs = in_sizes[8] / DD;

    int LA = (PL + 7) / 8,  LN = (NL + 63) / 64;
    int QA = (PQ + 7) / 8,  QN = (NQ + 63) / 64;

    int grid = 1 + LA * LN + QA * QN + 1 + nRows;
    k_main<<<grid, 256>>>(logits, labels, nRows, V,
                          lA, lP, lN, PL, NL, LA, LN,
                          qA, qP, qN, PQ, NQ, QA, QN,
                          sE, Bs);
    k_fin<<<1, 512>>>(logits, V, (float*)d_out, PL, PQ, 1.0f / PL, 1.0f / PQ, Bs);
}

// round 8
// speedup vs baseline: 1.4115x; 1.4115x over previous
#include <cuda_runtime.h>

#define DD 768
#define Q6 6
#define INV_T 14.285714285714286f
#define CSHIFT 14.285714285714286f
#define MAXROWS 8192
#define SEG 2
#define NMLM 1536

// ---- persistent device state (zero at load; k_fin resets what k_init/k_main dirty) ----
static __device__ float g_S[512];
static __device__ float g_pos[512];
static __device__ float g_sonnet_sum;
static __device__ int   g_rowIdx[MAXROWS];
static __device__ int   g_labArr[MAXROWS];
static __device__ float g_rowS[MAXROWS];
static __device__ float g_labLogit[MAXROWS];
static __device__ int   g_cnt;

__device__ __forceinline__ float wsum(float v) {
    v += __shfl_xor_sync(0xffffffffu, v, 16);
    v += __shfl_xor_sync(0xffffffffu, v, 8);
    v += __shfl_xor_sync(0xffffffffu, v, 4);
    v += __shfl_xor_sync(0xffffffffu, v, 2);
    v += __shfl_xor_sync(0xffffffffu, v, 1);
    return v;
}

// per-lane 24 floats of a 768-float row, coalesced float4 pattern
__device__ __forceinline__ float load_chunk(const float* __restrict__ row, float* v, int lane) {
    const float4* r4 = (const float4*)row;
    float sq = 0.f;
#pragma unroll
    for (int q = 0; q < Q6; ++q) {
        float4 t = r4[lane + 32 * q];
        v[4*q+0] = t.x; v[4*q+1] = t.y; v[4*q+2] = t.z; v[4*q+3] = t.w;
        sq = fmaf(t.x, t.x, sq); sq = fmaf(t.y, t.y, sq);
        sq = fmaf(t.z, t.z, sq); sq = fmaf(t.w, t.w, sq);
    }
    return sq;
}

__device__ __forceinline__ float sumsq_row(const float* __restrict__ row, int lane) {
    const float4* r4 = (const float4*)row;
    float sq = 0.f;
#pragma unroll
    for (int q = 0; q < Q6; ++q) {
        float4 t = r4[lane + 32 * q];
        sq = fmaf(t.x, t.x, sq); sq = fmaf(t.y, t.y, sq);
        sq = fmaf(t.z, t.z, sq); sq = fmaf(t.w, t.w, sq);
    }
    return sq;
}

// ---------------- k_init: dtype detect (per-block, L2-hot) + compact valid rows ----------------
__global__ void __launch_bounds__(256) k_init(const void* __restrict__ labels, int nRows) {
    __shared__ int s_ok;
    int tid = threadIdx.x;
    if (tid == 0) s_ok = 1;
    __syncthreads();
    // int64 little-endian: odd int32 words are sign extensions (0 or -1).
    // Every block computes the same answer from the same data -> consistent.
    const int2* p2 = (const int2*)labels;
    int half = nRows >> 1;
    bool bad = false;
    for (int i = tid; i < half; i += 256) {
        int hi = p2[i].y;
        if (hi != 0 && hi != -1) bad = true;
    }
    if (bad) s_ok = 0;   // benign race: all writers store 0
    __syncthreads();
    int lab64 = s_ok;
    const int* p = (const int*)labels;
    int gtid = blockIdx.x * 256 + tid;
    int gsz  = gridDim.x * 256;
    for (int r = gtid; r < nRows; r += gsz) {
        int lab = lab64 ? (int)((const long long*)labels)[r] : p[r];
        if (lab >= 0) {
            int slot = atomicAdd(&g_cnt, 1);
            g_rowIdx[slot] = r;
            g_labArr[slot] = lab;
            g_rowS[slot]   = 0.f;
        }
    }
}

// ---------------- role: MLM segment stream (SEG=2 halves per valid row) ----------------
__device__ void mlm_seg(const float* __restrict__ logits, int V, int bid) {
    int nseg = g_cnt * SEG;          // final: k_init completed (graph edge)
    int n2   = V >> 1;
    int half = (n2 + SEG - 1) / SEG;
    for (int s = bid; s < nseg; s += NMLM) {
        int slot = s >> 1, sg = s & 1;
        int row  = g_rowIdx[slot];
        const float2* x2 = (const float2*)(logits + (size_t)row * V);  // 8B-aligned always
        int start = sg * half;
        int end   = min(n2, start + half);
        float a0 = 0.f, a1 = 0.f;
        int i = start + threadIdx.x;
        int endu = end - 256 * 7;
        for (; i < endu; i += 256 * 8) {
            float2 v[8];
#pragma unroll
            for (int u = 0; u < 8; ++u) v[u] = x2[i + 256 * u];
#pragma unroll
            for (int u = 0; u < 8; ++u) { a0 += __expf(v[u].x); a1 += __expf(v[u].y); }
        }
        for (; i < end; i += 256) { float2 v = x2[i]; a0 += __expf(v.x); a1 += __expf(v.y); }
        if (sg == 0 && threadIdx.x == 0) {
            if (V & 1) a0 += __expf(logits[(size_t)row * V + V - 1]);  // odd-V tail
            g_labLogit[slot] = logits[(size_t)row * V + g_labArr[slot]];
        }
        float w = wsum(a0 + a1);
        if ((threadIdx.x & 31) == 0) atomicAdd(&g_rowS[slot], w);
    }
}

// ------- role: InfoNCE tile (8 anchors x <=64 negatives) -------
__device__ void infonce_block(const float* __restrict__ A,
                              const float* __restrict__ Pp,
                              const float* __restrict__ Ng,
                              int nP, int nN, int ga, int gn, int Sbase) {
    __shared__ float inv_nn[64];
    int tid = threadIdx.x, w = tid >> 5, lane = tid & 31;
    int nBase = gn << 6;
    int nCnt = min(64, nN - nBase);
    for (int j = w; j < nCnt; j += 8) {
        float sq = wsum(sumsq_row(Ng + (size_t)(nBase + j) * DD, lane));
        if (lane == 0) inv_nn[j] = rsqrtf(fmaxf(sq, 1e-24f));
    }
    __syncthreads();
    int a = ga * 8 + w;
    if (a >= nP) return;
    float av[24];
    float sq = wsum(load_chunk(A + (size_t)a * DD, av, lane));
    float inv = rsqrtf(fmaxf(sq, 1e-24f));
#pragma unroll
    for (int i = 0; i < 24; ++i) av[i] *= inv;

    float acc = 0.f;
    for (int j = 0; j < nCnt; ++j) {
        const float4* r4 = (const float4*)(Ng + (size_t)(nBase + j) * DD);
        float d = 0.f;
#pragma unroll
        for (int q = 0; q < Q6; ++q) {
            float4 t = r4[lane + 32 * q];
            d = fmaf(av[4*q+0], t.x, d);
            d = fmaf(av[4*q+1], t.y, d);
            d = fmaf(av[4*q+2], t.z, d);
            d = fmaf(av[4*q+3], t.w, d);
        }
        d = wsum(d);
        acc += __expf(fmaf(d, inv_nn[j] * INV_T, -CSHIFT));  // sim <= 1/T, no max needed
    }
    if (gn == 0) {  // streamed positive (no second register array)
        const float4* r4 = (const float4*)(Pp + (size_t)a * DD);
        float dp = 0.f, psq = 0.f;
#pragma unroll
        for (int q = 0; q < Q6; ++q) {
            float4 t = r4[lane + 32 * q];
            dp = fmaf(av[4*q+0], t.x, dp);
            dp = fmaf(av[4*q+1], t.y, dp);
            dp = fmaf(av[4*q+2], t.z, dp);
            dp = fmaf(av[4*q+3], t.w, dp);
            psq = fmaf(t.x, t.x, psq); psq = fmaf(t.y, t.y, psq);
            psq = fmaf(t.z, t.z, psq); psq = fmaf(t.w, t.w, psq);
        }
        dp = wsum(dp); psq = wsum(psq);
        float pos = dp * rsqrtf(fmaxf(psq, 1e-24f)) * INV_T;
        acc += __expf(pos - CSHIFT);
        if (lane == 0) g_pos[Sbase + a] = pos;
    }
    if (lane == 0) atomicAdd(&g_S[Sbase + a], acc);
}

// ---------------- role: sonnet (single block) ----------------
__device__ void sonnet_block(const float* __restrict__ E, int Bs) {
    __shared__ float invn[32];
    int tid = threadIdx.x, w = tid >> 5, lane = tid & 31;
    for (int i = w; i < Bs; i += 8) {
        float sq = wsum(sumsq_row(E + (size_t)i * DD, lane));
        if (lane == 0) invn[i] = rsqrtf(fmaxf(sq, 1e-24f));
    }
    __syncthreads();
    for (int i = w; i < Bs; i += 8) {
        float xv[24];
        load_chunk(E + (size_t)i * DD, xv, lane);
        float si = invn[i];
        float acc = 0.f, diag = 0.f;
        for (int j = 0; j < Bs; ++j) {
            const float4* r4 = (const float4*)(E + (size_t)j * DD);
            float d = 0.f;
#pragma unroll
            for (int q = 0; q < Q6; ++q) {
                float4 t = r4[lane + 32 * q];
                d = fmaf(xv[4*q+0], t.x, d);
                d = fmaf(xv[4*q+1], t.y, d);
                d = fmaf(xv[4*q+2], t.z, d);
                d = fmaf(xv[4*q+3], t.w, d);
            }
            d = wsum(d);
            float sim = d * si * invn[j] * INV_T;
            acc += __expf(sim - CSHIFT);
            if (j == i) diag = sim;
        }
        if (lane == 0) atomicAdd(&g_sonnet_sum, logf(acc) + CSHIFT - diag);
    }
}

// ---------------- fused main kernel ----------------
// MLM segment blocks at LOW bids (critical path streams first); contrastive at tail.
__global__ void __launch_bounds__(256)
k_main(const float* __restrict__ logits, int V,
       const float* __restrict__ lA, const float* __restrict__ lP,
       const float* __restrict__ lN, int PL, int NL, int LA, int LN,
       const float* __restrict__ qA, const float* __restrict__ qP,
       const float* __restrict__ qN, int PQ, int NQ, int QA, int QN,
       const float* __restrict__ sE, int Bs) {
    int b = blockIdx.x;
    if (b < NMLM) { mlm_seg(logits, V, b); return; }
    b -= NMLM;
    if (b < LA * LN) { infonce_block(lA, lP, lN, PL, NL, b / LN, b % LN, 0); return; }
    b -= LA * LN;
    if (b < QA * QN) { infonce_block(qA, qP, qN, PQ, NQ, b / QN, b % QN, PL); return; }
    sonnet_block(sE, Bs);
}

// ---------------- finalize + state reset (small contiguous reads only) ----------------
__global__ void k_fin(float* __restrict__ out, int PL, int PQ,
                      float invPL, float invPQ, int Bs) {
    __shared__ float red[512];
    int tid = threadIdx.x;
    int nv = g_cnt;
    float invNv = 1.0f / (float)max(nv, 1);
    float acc = 0.f;
    for (int i = tid; i < nv; i += 512)
        acc += logf(g_rowS[i]) - g_labLogit[i];
    acc *= 0.5f * invNv;
    for (int i = tid; i < PL + PQ; i += 512) {
        float wgt = (i < PL) ? (0.2f * invPL) : (0.2f * invPQ);
        acc += wgt * (logf(g_S[i]) + CSHIFT - g_pos[i]);
    }
    red[tid] = acc;
    __syncthreads();
    for (int s = 256; s; s >>= 1) {
        if (tid < s) red[tid] += red[tid + s];
        __syncthreads();
    }
    if (tid == 0)
        out[0] = red[0] + 0.1f * g_sonnet_sum / (float)Bs;
    __syncthreads();
    // reset for next graph replay (all reads above complete)
    for (int i = tid; i < 512; i += 512) { g_S[i] = 0.f; g_pos[i] = 0.f; }
    if (tid == 0) { g_sonnet_sum = 0.f; g_cnt = 0; }
}

extern "C" void kernel_launch(void* const* d_in, const int* in_sizes, int n_in,
                              void* d_out, int out_size) {
    const float* logits = (const float*)d_in[0];
    const void*  labels = d_in[1];
    const float* lA = (const float*)d_in[2];
    const float* lP = (const float*)d_in[3];
    const float* lN = (const float*)d_in[4];
    const float* qA = (const float*)d_in[5];
    const float* qP = (const float*)d_in[6];
    const float* qN = (const float*)d_in[7];
    const float* sE = (const float*)d_in[8];

    int nRows = in_sizes[1];
    int V  = in_sizes[0] / nRows;
    int PL = in_sizes[2] / DD, NL = in_sizes[4] / DD;
    int PQ = in_sizes[5] / DD, NQ = in_sizes[7] / DD;
    int Bs = in_sizes[8] / DD;

    int LA = (PL + 7) / 8,  LN = (NL + 63) / 64;
    int QA = (PQ + 7) / 8,  QN = (NQ + 63) / 64;

    k_init<<<32, 256>>>(labels, nRows);
    int grid = NMLM + LA * LN + QA * QN + 1;
    k_main<<<grid, 256>>>(logits, V,
                          lA, lP, lN, PL, NL, LA, LN,
                          qA, qP, qN, PQ, NQ, QA, QN,
                          sE, Bs);
    k_fin<<<1, 512>>>((float*)d_out, PL, PQ, 1.0f / PL, 1.0f / PQ, Bs);
}

// round 9
// speedup vs baseline: 1.6262x; 1.1521x over previous
#include <cuda_runtime.h>

#define DD 768
#define Q6 6
#define INV_T 14.285714285714286f
#define CSHIFT 14.285714285714286f
#define MAXROWS 8192
#define NMLM 1536

// ---- persistent device state (zero at load; finalize resets what gets dirtied) ----
static __device__ float g_S[512];
static __device__ float g_pos[512];
static __device__ float g_sonnet_sum;
static __device__ int   g_rowIdx[MAXROWS];
static __device__ int   g_labArr[MAXROWS];
static __device__ float g_rowS[MAXROWS];
static __device__ float g_labLogit[MAXROWS];
static __device__ int   g_cnt;
static __device__ int   g_done;
static __device__ float g_invLN[256], g_invQN[128];
static __device__ float g_invLA[256], g_invQA[128];
static __device__ float g_invLP[256], g_invQP[128];
static __device__ float g_invSon[32];

__device__ __forceinline__ float wsum(float v) {
    v += __shfl_xor_sync(0xffffffffu, v, 16);
    v += __shfl_xor_sync(0xffffffffu, v, 8);
    v += __shfl_xor_sync(0xffffffffu, v, 4);
    v += __shfl_xor_sync(0xffffffffu, v, 2);
    v += __shfl_xor_sync(0xffffffffu, v, 1);
    return v;
}

// per-lane 24 floats of a 768-float row (coalesced: float4 index = lane + 32q)
__device__ __forceinline__ void load_vec(const float* __restrict__ row, float* v, int lane) {
    const float4* r4 = (const float4*)row;
#pragma unroll
    for (int q = 0; q < Q6; ++q) {
        float4 t = r4[lane + 32 * q];
        v[4*q+0] = t.x; v[4*q+1] = t.y; v[4*q+2] = t.z; v[4*q+3] = t.w;
    }
}

__device__ __forceinline__ float sumsq_row(const float* __restrict__ row, int lane) {
    const float4* r4 = (const float4*)row;
    float sq = 0.f;
#pragma unroll
    for (int q = 0; q < Q6; ++q) {
        float4 t = r4[lane + 32 * q];
        sq = fmaf(t.x, t.x, sq); sq = fmaf(t.y, t.y, sq);
        sq = fmaf(t.z, t.z, sq); sq = fmaf(t.w, t.w, sq);
    }
    return sq;
}

// ---------------- k_init: dtype detect + compact valid rows + ALL inverse norms ----------------
__global__ void __launch_bounds__(256) k_init(const void* __restrict__ labels, int nRows,
    const float* __restrict__ lA, const float* __restrict__ lP, const float* __restrict__ lN,
    int PL, int NL,
    const float* __restrict__ qA, const float* __restrict__ qP, const float* __restrict__ qN,
    int PQ, int NQ,
    const float* __restrict__ sE, int Bs)
{
    __shared__ int s_ok;
    int tid = threadIdx.x;
    if (tid == 0) s_ok = 1;
    __syncthreads();
    // int64 little-endian: odd int32 words are sign extensions (0 or -1).
    const int2* p2 = (const int2*)labels;
    int half = nRows >> 1;
    bool bad = false;
    for (int i = tid; i < half; i += 256) {
        int hi = p2[i].y;
        if (hi != 0 && hi != -1) bad = true;
    }
    if (bad) s_ok = 0;   // benign race: all writers store 0
    __syncthreads();
    int lab64 = s_ok;
    const int* p = (const int*)labels;
    int gtid = blockIdx.x * 256 + tid;
    int gsz  = gridDim.x * 256;
    for (int r = gtid; r < nRows; r += gsz) {
        int lab = lab64 ? (int)((const long long*)labels)[r] : p[r];
        if (lab >= 0) {
            int slot = atomicAdd(&g_cnt, 1);
            g_rowIdx[slot] = r;
            g_labArr[slot] = lab;
            g_rowS[slot]   = 0.f;
        }
    }
    // inverse norms: one warp per row over the concatenated task list
    int lane = tid & 31;
    int gw = gtid >> 5;
    int nw = gsz >> 5;
    int e0 = NL, e1 = e0 + NQ, e2 = e1 + PL, e3 = e2 + PQ, e4 = e3 + PL, e5 = e4 + PQ, e6 = e5 + Bs;
    for (int r = gw; r < e6; r += nw) {
        const float* src; float* dst;
        if      (r < e0) { src = lN + (size_t)r * DD;        dst = g_invLN + r; }
        else if (r < e1) { src = qN + (size_t)(r-e0) * DD;   dst = g_invQN + (r-e0); }
        else if (r < e2) { src = lA + (size_t)(r-e1) * DD;   dst = g_invLA + (r-e1); }
        else if (r < e3) { src = qA + (size_t)(r-e2) * DD;   dst = g_invQA + (r-e2); }
        else if (r < e4) { src = lP + (size_t)(r-e3) * DD;   dst = g_invLP + (r-e3); }
        else if (r < e5) { src = qP + (size_t)(r-e4) * DD;   dst = g_invQP + (r-e4); }
        else             { src = sE + (size_t)(r-e5) * DD;   dst = g_invSon + (r-e5); }
        float sq = wsum(sumsq_row(src, lane));
        if (lane == 0) *dst = rsqrtf(fmaxf(sq, 1e-24f));
    }
}

// ---------------- role: MLM segment stream (2 halves per valid row) ----------------
__device__ void mlm_seg(const float* __restrict__ logits, int V, int bid) {
    int nseg = g_cnt * 2;
    int n2   = V >> 1;
    int half = (n2 + 1) >> 1;
    for (int s = bid; s < nseg; s += NMLM) {
        int slot = s >> 1, sg = s & 1;
        int row  = g_rowIdx[slot];
        const float2* x2 = (const float2*)(logits + (size_t)row * V);  // 8B-aligned (V even)
        int start = sg * half;
        int end   = sg ? n2 : half;
        float a0 = 0.f, a1 = 0.f;
        int i = start + threadIdx.x;
        int endu = end - 256 * 7;
        for (; i < endu; i += 256 * 8) {
            float2 v[8];
#pragma unroll
            for (int u = 0; u < 8; ++u) v[u] = x2[i + 256 * u];
#pragma unroll
            for (int u = 0; u < 8; ++u) { a0 += __expf(v[u].x); a1 += __expf(v[u].y); }
        }
        for (; i < end; i += 256) { float2 v = x2[i]; a0 += __expf(v.x); a1 += __expf(v.y); }
        if (sg == 0 && threadIdx.x == 0) {
            const float* x = logits + (size_t)row * V;
            if (V & 1) a0 += __expf(x[V - 1]);
            g_labLogit[slot] = x[g_labArr[slot]];
        }
        float w = wsum(a0 + a1);
        if ((threadIdx.x & 31) == 0) atomicAdd(&g_rowS[slot], w);
    }
}

// ------- role: InfoNCE tile (8 anchors x <=64 negatives), norms precomputed -------
__device__ void infonce_block(const float* __restrict__ A,
                              const float* __restrict__ Pp,
                              const float* __restrict__ Ng,
                              const float* __restrict__ invA,
                              const float* __restrict__ invP,
                              const float* __restrict__ invN,
                              int nP, int nN, int ga, int gn, int Sbase) {
    int tid = threadIdx.x, w = tid >> 5, lane = tid & 31;
    int nBase = gn << 6;
    int nCnt = min(64, nN - nBase);
    int a = ga * 8 + w;
    if (a >= nP) return;       // function return only; no syncthreads inside
    float av[24];
    load_vec(A + (size_t)a * DD, av, lane);
    float scale = invA[a] * INV_T;     // fold temperature into the anchor
#pragma unroll
    for (int i = 0; i < 24; ++i) av[i] *= scale;

    float acc = 0.f;
    int j = 0;
    for (; j + 4 <= nCnt; j += 4) {
        const float4* r0 = (const float4*)(Ng + (size_t)(nBase + j + 0) * DD);
        const float4* r1 = (const float4*)(Ng + (size_t)(nBase + j + 1) * DD);
        const float4* r2 = (const float4*)(Ng + (size_t)(nBase + j + 2) * DD);
        const float4* r3 = (const float4*)(Ng + (size_t)(nBase + j + 3) * DD);
        float d0 = 0.f, d1 = 0.f, d2 = 0.f, d3 = 0.f;
#pragma unroll
        for (int q = 0; q < Q6; ++q) {
            int ix = lane + 32 * q;
            float4 t0 = r0[ix], t1 = r1[ix], t2 = r2[ix], t3 = r3[ix];
            d0 = fmaf(av[4*q+0], t0.x, d0); d0 = fmaf(av[4*q+1], t0.y, d0);
            d0 = fmaf(av[4*q+2], t0.z, d0); d0 = fmaf(av[4*q+3], t0.w, d0);
            d1 = fmaf(av[4*q+0], t1.x, d1); d1 = fmaf(av[4*q+1], t1.y, d1);
            d1 = fmaf(av[4*q+2], t1.z, d1); d1 = fmaf(av[4*q+3], t1.w, d1);
            d2 = fmaf(av[4*q+0], t2.x, d2); d2 = fmaf(av[4*q+1], t2.y, d2);
            d2 = fmaf(av[4*q+2], t2.z, d2); d2 = fmaf(av[4*q+3], t2.w, d2);
            d3 = fmaf(av[4*q+0], t3.x, d3); d3 = fmaf(av[4*q+1], t3.y, d3);
            d3 = fmaf(av[4*q+2], t3.z, d3); d3 = fmaf(av[4*q+3], t3.w, d3);
        }
        d0 = wsum(d0); d1 = wsum(d1); d2 = wsum(d2); d3 = wsum(d3);  // chains pipeline
        acc += __expf(fmaf(d0, invN[nBase + j + 0], -CSHIFT));
        acc += __expf(fmaf(d1, invN[nBase + j + 1], -CSHIFT));
        acc += __expf(fmaf(d2, invN[nBase + j + 2], -CSHIFT));
        acc += __expf(fmaf(d3, invN[nBase + j + 3], -CSHIFT));
    }
    for (; j < nCnt; ++j) {
        const float4* r4 = (const float4*)(Ng + (size_t)(nBase + j) * DD);
        float d = 0.f;
#pragma unroll
        for (int q = 0; q < Q6; ++q) {
            float4 t = r4[lane + 32 * q];
            d = fmaf(av[4*q+0], t.x, d); d = fmaf(av[4*q+1], t.y, d);
            d = fmaf(av[4*q+2], t.z, d); d = fmaf(av[4*q+3], t.w, d);
        }
        d = wsum(d);
        acc += __expf(fmaf(d, invN[nBase + j], -CSHIFT));
    }
    if (gn == 0) {  // positive term once per anchor (streamed, norm precomputed)
        const float4* r4 = (const float4*)(Pp + (size_t)a * DD);
        float dp = 0.f;
#pragma unroll
        for (int q = 0; q < Q6; ++q) {
            float4 t = r4[lane + 32 * q];
            dp = fmaf(av[4*q+0], t.x, dp); dp = fmaf(av[4*q+1], t.y, dp);
            dp = fmaf(av[4*q+2], t.z, dp); dp = fmaf(av[4*q+3], t.w, dp);
        }
        dp = wsum(dp);
        float pos = dp * invP[a];       // INV_T already folded into av
        acc += __expf(pos - CSHIFT);
        if (lane == 0) g_pos[Sbase + a] = pos;
    }
    if (lane == 0) atomicAdd(&g_S[Sbase + a], acc);
}

// ---------------- role: sonnet (single block), norms precomputed ----------------
__device__ void sonnet_block(const float* __restrict__ E, int Bs) {
    int tid = threadIdx.x, w = tid >> 5, lane = tid & 31;
    for (int i = w; i < Bs; i += 8) {
        float xv[24];
        load_vec(E + (size_t)i * DD, xv, lane);
        float s = g_invSon[i] * INV_T;
#pragma unroll
        for (int k = 0; k < 24; ++k) xv[k] *= s;
        float acc = 0.f, diag = 0.f;
        for (int j = 0; j < Bs; ++j) {
            const float4* r4 = (const float4*)(E + (size_t)j * DD);
            float d = 0.f;
#pragma unroll
            for (int q = 0; q < Q6; ++q) {
                float4 t = r4[lane + 32 * q];
                d = fmaf(xv[4*q+0], t.x, d); d = fmaf(xv[4*q+1], t.y, d);
                d = fmaf(xv[4*q+2], t.z, d); d = fmaf(xv[4*q+3], t.w, d);
            }
            d = wsum(d);
            float sim = d * g_invSon[j];
            acc += __expf(sim - CSHIFT);
            if (j == i) diag = sim;
        }
        if (lane == 0) atomicAdd(&g_sonnet_sum, logf(acc) + CSHIFT - diag);
    }
}

// ---------------- finalize (executed by the last block to finish) ----------------
__device__ void finalize(float* __restrict__ out, int PL, int PQ,
                         float invPL, float invPQ, int Bs) {
    __shared__ float red[256];
    int tid = threadIdx.x;
    int nv = g_cnt;
    float acc = 0.f;
    for (int i = tid; i < nv; i += 256)
        acc += logf(g_rowS[i]) - g_labLogit[i];
    acc *= 0.5f / (float)max(nv, 1);
    for (int i = tid; i < PL + PQ; i += 256) {
        float wgt = (i < PL) ? (0.2f * invPL) : (0.2f * invPQ);
        acc += wgt * (logf(g_S[i]) + CSHIFT - g_pos[i]);
    }
    red[tid] = acc;
    __syncthreads();
    for (int s = 128; s; s >>= 1) {
        if (tid < s) red[tid] += red[tid + s];
        __syncthreads();
    }
    if (tid == 0)
        out[0] = red[0] + 0.1f * g_sonnet_sum / (float)Bs;
    __syncthreads();
    // reset for next graph replay (all reads above complete)
    for (int i = tid; i < 512; i += 256) { g_S[i] = 0.f; g_pos[i] = 0.f; }
    if (tid == 0) { g_sonnet_sum = 0.f; g_cnt = 0; g_done = 0; }
}

// ---------------- fused main kernel ----------------
// Contrastive blocks FIRST (start at t=0, hide under the MLM stream); MLM segs after.
__global__ void __launch_bounds__(256)
k_main(const float* __restrict__ logits, int V,
       const float* __restrict__ lA, const float* __restrict__ lP,
       const float* __restrict__ lN, int PL, int NL, int LA, int LN,
       const float* __restrict__ qA, const float* __restrict__ qP,
       const float* __restrict__ qN, int PQ, int NQ, int QA, int QN,
       const float* __restrict__ sE, int Bs,
       float* __restrict__ out, float invPL, float invPQ) {
    int b = blockIdx.x;
    int C1 = LA * LN, C2 = QA * QN;
    if (b < C1) {
        infonce_block(lA, lP, lN, g_invLA, g_invLP, g_invLN, PL, NL, b / LN, b % LN, 0);
    } else if (b < C1 + C2) {
        int bb = b - C1;
        infonce_block(qA, qP, qN, g_invQA, g_invQP, g_invQN, PQ, NQ, bb / QN, bb % QN, PL);
    } else if (b == C1 + C2) {
        sonnet_block(sE, Bs);
    } else {
        mlm_seg(logits, V, b - (C1 + C2 + 1));
    }
    // last-block-done finalization
    __syncthreads();
    __threadfence();
    __shared__ int s_last;
    if (threadIdx.x == 0)
        s_last = (atomicAdd(&g_done, 1) == (int)gridDim.x - 1) ? 1 : 0;
    __syncthreads();
    if (s_last) {
        __threadfence();
        finalize(out, PL, PQ, invPL, invPQ, Bs);
    }
}

extern "C" void kernel_launch(void* const* d_in, const int* in_sizes, int n_in,
                              void* d_out, int out_size) {
    const float* logits = (const float*)d_in[0];
    const void*  labels = d_in[1];
    const float* lA = (const float*)d_in[2];
    const float* lP = (const float*)d_in[3];
    const float* lN = (const float*)d_in[4];
    const float* qA = (const float*)d_in[5];
    const float* qP = (const float*)d_in[6];
    const float* qN = (const float*)d_in[7];
    const float* sE = (const float*)d_in[8];

    int nRows = in_sizes[1];
    int V  = in_sizes[0] / nRows;
    int PL = in_sizes[2] / DD, NL = in_sizes[4] / DD;
    int PQ = in_sizes[5] / DD, NQ = in_sizes[7] / DD;
    int Bs = in_sizes[8] / DD;

    int LA = (PL + 7) / 8,  LN = (NL + 63) / 64;
    int QA = (PQ + 7) / 8,  QN = (NQ + 63) / 64;

    k_init<<<32, 256>>>(labels, nRows, lA, lP, lN, PL, NL,
                        qA, qP, qN, PQ, NQ, sE, Bs);
    int grid = LA * LN + QA * QN + 1 + NMLM;
    k_main<<<grid, 256>>>(logits, V,
                          lA, lP, lN, PL, NL, LA, LN,
                          qA, qP, qN, PQ, NQ, QA, QN,
                          sE, Bs,
                          (float*)d_out, 1.0f / PL, 1.0f / PQ);
}

// round 12
// speedup vs baseline: 1.7761x; 1.0921x over previous
#include <cuda_runtime.h>

#define DD 768
#define Q6 6
#define INV_T 14.285714285714286f
#define CSHIFT 14.285714285714286f
#define MAXROWS 8192
#define NMLM 1536
#define NINIT 110

// ---- persistent device state (zero at load; finalize resets what gets dirtied) ----
static __device__ float g_S[512];
static __device__ float g_pos[512];
static __device__ float g_sonnet_sum;
static __device__ int   g_rowIdx[MAXROWS];
static __device__ int   g_labArr[MAXROWS];
static __device__ float g_rowS[MAXROWS];
static __device__ float g_labLogit[MAXROWS];
static __device__ int   g_cnt;
static __device__ int   g_done;
static __device__ float g_invLN[256], g_invQN[128];
static __device__ float g_invLA[256], g_invQA[128];
static __device__ float g_invLP[256], g_invQP[128];
static __device__ float g_invSon[32];

__device__ __forceinline__ float wsum(float v) {
    v += __shfl_xor_sync(0xffffffffu, v, 16);
    v += __shfl_xor_sync(0xffffffffu, v, 8);
    v += __shfl_xor_sync(0xffffffffu, v, 4);
    v += __shfl_xor_sync(0xffffffffu, v, 2);
    v += __shfl_xor_sync(0xffffffffu, v, 1);
    return v;
}

__device__ __forceinline__ float sumsq_row(const float* __restrict__ row, int lane) {
    const float4* r4 = (const float4*)row;
    float sq = 0.f;
#pragma unroll
    for (int q = 0; q < Q6; ++q) {
        float4 t = r4[lane + 32 * q];
        sq = fmaf(t.x, t.x, sq); sq = fmaf(t.y, t.y, sq);
        sq = fmaf(t.z, t.z, sq); sq = fmaf(t.w, t.w, sq);
    }
    return sq;
}

// ---------------- k_init: dtype detect + compact valid rows + ALL inverse norms ----------------
__global__ void __launch_bounds__(256) k_init(const void* __restrict__ labels, int nRows,
    const float* __restrict__ lA, const float* __restrict__ lP, const float* __restrict__ lN,
    int PL, int NL,
    const float* __restrict__ qA, const float* __restrict__ qP, const float* __restrict__ qN,
    int PQ, int NQ,
    const float* __restrict__ sE, int Bs)
{
    __shared__ int s_ok;
    int tid = threadIdx.x;
    if (tid == 0) s_ok = 1;
    __syncthreads();
    // int64 little-endian: odd int32 words are sign extensions (0 or -1).
    const int2* p2 = (const int2*)labels;
    int half = nRows >> 1;
    bool bad = false;
    for (int i = tid; i < half; i += 256) {
        int hi = p2[i].y;
        if (hi != 0 && hi != -1) bad = true;
    }
    if (bad) s_ok = 0;   // benign race: all writers store 0
    __syncthreads();
    int lab64 = s_ok;
    const int* p = (const int*)labels;
    int gtid = blockIdx.x * 256 + tid;
    int gsz  = NINIT * 256;
    for (int r = gtid; r < nRows; r += gsz) {
        int lab = lab64 ? (int)((const long long*)labels)[r] : p[r];
        if (lab >= 0) {
            int slot = atomicAdd(&g_cnt, 1);
            g_rowIdx[slot] = r;
            g_labArr[slot] = lab;
            g_rowS[slot]   = 0.f;
        }
    }
    // inverse norms: one warp per row over the concatenated task list (880 rows = 880 warps)
    int lane = tid & 31;
    int gw = gtid >> 5;
    int nw = gsz >> 5;
    int e0 = NL, e1 = e0 + NQ, e2 = e1 + PL, e3 = e2 + PQ, e4 = e3 + PL, e5 = e4 + PQ, e6 = e5 + Bs;
    for (int r = gw; r < e6; r += nw) {
        const float* src; float* dst;
        if      (r < e0) { src = lN + (size_t)r * DD;        dst = g_invLN + r; }
        else if (r < e1) { src = qN + (size_t)(r-e0) * DD;   dst = g_invQN + (r-e0); }
        else if (r < e2) { src = lA + (size_t)(r-e1) * DD;   dst = g_invLA + (r-e1); }
        else if (r < e3) { src = qA + (size_t)(r-e2) * DD;   dst = g_invQA + (r-e2); }
        else if (r < e4) { src = lP + (size_t)(r-e3) * DD;   dst = g_invLP + (r-e3); }
        else if (r < e5) { src = qP + (size_t)(r-e4) * DD;   dst = g_invQP + (r-e4); }
        else             { src = sE + (size_t)(r-e5) * DD;   dst = g_invSon + (r-e5); }
        float sq = wsum(sumsq_row(src, lane));
        if (lane == 0) *dst = rsqrtf(fmaxf(sq, 1e-24f));
    }
}

// ---------------- role: MLM segment stream (2 halves per valid row) ----------------
// float4 loads aligned to 16B, 2-stage software pipeline (8 loads in flight/thread).
__device__ void mlm_seg(const float* __restrict__ logits, int V, int bid) {
    int nseg = g_cnt * 2;
    int mid  = V >> 1;
    const float4* __restrict__ x4 = (const float4*)logits;  // base 256B-aligned
    for (int s = bid; s < nseg; s += NMLM) {
        int slot = s >> 1, sg = s & 1;
        int row  = g_rowIdx[slot];
        long long e0 = (long long)row * V + (sg ? mid : 0);
        long long e1 = (long long)row * V + (sg ? V   : mid);
        int f0 = (int)((e0 + 3) >> 2);   // first full float4
        int f1 = (int)(e1 >> 2);         // end float4 (exclusive)
        float a0 = 0.f, a1 = 0.f, a2 = 0.f, a3 = 0.f;
        if (threadIdx.x == 0) {          // scalar head/tail (<=3 elems each) + label logit
            long long hEnd = ((long long)f0) << 2; if (hEnd > e1) hEnd = e1;
            for (long long e = e0; e < hEnd; ++e) a0 += __expf(logits[e]);
            long long tBeg = ((long long)f1) << 2; if (tBeg < e0) tBeg = e0;
            for (long long e = tBeg; e < e1; ++e) a1 += __expf(logits[e]);
            if (sg == 0) g_labLogit[slot] = logits[(long long)row * V + g_labArr[slot]];
        }
#define LD1(v, ix) if ((ix) < f1) v = x4[ix]
#define EX1(v, ix) if ((ix) < f1) { a0 += __expf(v.x); a1 += __expf(v.y); \
                                    a2 += __expf(v.z); a3 += __expf(v.w); }
        const float4 z4 = {0.f, 0.f, 0.f, 0.f};
        int ia = f0 + threadIdx.x;
        float4 va0 = z4, va1 = z4, va2 = z4, va3 = z4;
        LD1(va0, ia); LD1(va1, ia + 256); LD1(va2, ia + 512); LD1(va3, ia + 768);
        int ib = ia + 1024;
        while (ib < f1) {
            float4 vb0 = z4, vb1 = z4, vb2 = z4, vb3 = z4;
            LD1(vb0, ib); LD1(vb1, ib + 256); LD1(vb2, ib + 512); LD1(vb3, ib + 768);
            EX1(va0, ia); EX1(va1, ia + 256); EX1(va2, ia + 512); EX1(va3, ia + 768);
            va0 = vb0; va1 = vb1; va2 = vb2; va3 = vb3;
            ia = ib; ib += 1024;
        }
        EX1(va0, ia); EX1(va1, ia + 256); EX1(va2, ia + 512); EX1(va3, ia + 768);
#undef LD1
#undef EX1
        float w = wsum(a0 + a1 + a2 + a3);
        if ((threadIdx.x & 31) == 0) atomicAdd(&g_rowS[slot], w);
    }
}

// ------- role: InfoNCE tile (8 anchors x <=64 negatives), anchor in SMEM -------
__device__ void infonce_block(const float* __restrict__ A,
                              const float* __restrict__ Pp,
                              const float* __restrict__ Ng,
                              const float* __restrict__ invA,
                              const float* __restrict__ invP,
                              const float* __restrict__ invN,
                              int nP, int nN, int ga, int gn, int Sbase,
                              float* __restrict__ s_anc /* this warp's 768-float slice */) {
    int tid = threadIdx.x, w = tid >> 5, lane = tid & 31;
    int nBase = gn << 6;
    int nCnt = min(64, nN - nBase);
    int a = ga * 8 + w;
    if (a >= nP) return;
    float scale = invA[a] * INV_T;     // fold temperature into the anchor
    {   // scaled anchor -> smem (per-lane slots; read back per-lane below)
        const float4* ar = (const float4*)(A + (size_t)a * DD);
        float4* sa = (float4*)s_anc;
#pragma unroll
        for (int q = 0; q < Q6; ++q) {
            float4 t = ar[lane + 32 * q];
            t.x *= scale; t.y *= scale; t.z *= scale; t.w *= scale;
            sa[lane + 32 * q] = t;
        }
    }
    __syncwarp();
    const float4* sa = (const float4*)s_anc;

    float acc = 0.f;
    int j = 0;
    for (; j + 4 <= nCnt; j += 4) {
        const float4* r0 = (const float4*)(Ng + (size_t)(nBase + j + 0) * DD);
        const float4* r1 = (const float4*)(Ng + (size_t)(nBase + j + 1) * DD);
        const float4* r2 = (const float4*)(Ng + (size_t)(nBase + j + 2) * DD);
        const float4* r3 = (const float4*)(Ng + (size_t)(nBase + j + 3) * DD);
        float d0 = 0.f, d1 = 0.f, d2 = 0.f, d3 = 0.f;
#pragma unroll
        for (int q = 0; q < Q6; ++q) {
            int ix = lane + 32 * q;
            float4 av = sa[ix];
            float4 t0 = r0[ix], t1 = r1[ix], t2 = r2[ix], t3 = r3[ix];
            d0 = fmaf(av.x, t0.x, d0); d0 = fmaf(av.y, t0.y, d0);
            d0 = fmaf(av.z, t0.z, d0); d0 = fmaf(av.w, t0.w, d0);
            d1 = fmaf(av.x, t1.x, d1); d1 = fmaf(av.y, t1.y, d1);
            d1 = fmaf(av.z, t1.z, d1); d1 = fmaf(av.w, t1.w, d1);
            d2 = fmaf(av.x, t2.x, d2); d2 = fmaf(av.y, t2.y, d2);
            d2 = fmaf(av.z, t2.z, d2); d2 = fmaf(av.w, t2.w, d2);
            d3 = fmaf(av.x, t3.x, d3); d3 = fmaf(av.y, t3.y, d3);
            d3 = fmaf(av.z, t3.z, d3); d3 = fmaf(av.w, t3.w, d3);
        }
        d0 = wsum(d0); d1 = wsum(d1); d2 = wsum(d2); d3 = wsum(d3);  // chains pipeline
        acc += __expf(fmaf(d0, invN[nBase + j + 0], -CSHIFT));
        acc += __expf(fmaf(d1, invN[nBase + j + 1], -CSHIFT));
        acc += __expf(fmaf(d2, invN[nBase + j + 2], -CSHIFT));
        acc += __expf(fmaf(d3, invN[nBase + j + 3], -CSHIFT));
    }
    for (; j < nCnt; ++j) {
        const float4* r4 = (const float4*)(Ng + (size_t)(nBase + j) * DD);
        float d = 0.f;
#pragma unroll
        for (int q = 0; q < Q6; ++q) {
            int ix = lane + 32 * q;
            float4 av = sa[ix];
            float4 t = r4[ix];
            d = fmaf(av.x, t.x, d); d = fmaf(av.y, t.y, d);
            d = fmaf(av.z, t.z, d); d = fmaf(av.w, t.w, d);
        }
        d = wsum(d);
        acc += __expf(fmaf(d, invN[nBase + j], -CSHIFT));
    }
    if (gn == 0) {  // positive term once per anchor
        const float4* r4 = (const float4*)(Pp + (size_t)a * DD);
        float dp = 0.f;
#pragma unroll
        for (int q = 0; q < Q6; ++q) {
            int ix = lane + 32 * q;
            float4 av = sa[ix];
            float4 t = r4[ix];
            dp = fmaf(av.x, t.x, dp); dp = fmaf(av.y, t.y, dp);
            dp = fmaf(av.z, t.z, dp); dp = fmaf(av.w, t.w, dp);
        }
        dp = wsum(dp);
        float pos = dp * invP[a];       // INV_T already folded into anchor
        acc += __expf(pos - CSHIFT);
        if (lane == 0) g_pos[Sbase + a] = pos;
    }
    if (lane == 0) atomicAdd(&g_S[Sbase + a], acc);
}

// ---------------- role: sonnet (single block), row in SMEM ----------------
__device__ void sonnet_block(const float* __restrict__ E, int Bs,
                             float* __restrict__ s_anc) {
    int tid = threadIdx.x, w = tid >> 5, lane = tid & 31;
    for (int i = w; i < Bs; i += 8) {
        float s = g_invSon[i] * INV_T;
        {
            const float4* ar = (const float4*)(E + (size_t)i * DD);
            float4* sa = (float4*)s_anc;
#pragma unroll
            for (int q = 0; q < Q6; ++q) {
                float4 t = ar[lane + 32 * q];
                t.x *= s; t.y *= s; t.z *= s; t.w *= s;
                sa[lane + 32 * q] = t;
            }
        }
        __syncwarp();
        const float4* sa = (const float4*)s_anc;
        float acc = 0.f, diag = 0.f;
        for (int j = 0; j < Bs; ++j) {
            const float4* r4 = (const float4*)(E + (size_t)j * DD);
            float d = 0.f;
#pragma unroll
            for (int q = 0; q < Q6; ++q) {
                int ix = lane + 32 * q;
                float4 av = sa[ix];
                float4 t = r4[ix];
                d = fmaf(av.x, t.x, d); d = fmaf(av.y, t.y, d);
                d = fmaf(av.z, t.z, d); d = fmaf(av.w, t.w, d);
            }
            d = wsum(d);
            float sim = d * g_invSon[j];
            acc += __expf(sim - CSHIFT);
            if (j == i) diag = sim;
        }
        if (lane == 0) atomicAdd(&g_sonnet_sum, logf(acc) + CSHIFT - diag);
        __syncwarp();
    }
}

// ---------------- finalize (executed by the last block to finish) ----------------
__device__ void finalize(float* __restrict__ out, int PL, int PQ,
                         float invPL, float invPQ, int Bs) {
    __shared__ float red[256];
    int tid = threadIdx.x;
    int nv = g_cnt;
    float acc = 0.f;
    for (int i = tid; i < nv; i += 256)
        acc += logf(g_rowS[i]) - g_labLogit[i];
    acc *= 0.5f / (float)max(nv, 1);
    for (int i = tid; i < PL + PQ; i += 256) {
        float wgt = (i < PL) ? (0.2f * invPL) : (0.2f * invPQ);
        acc += wgt * (logf(g_S[i]) + CSHIFT - g_pos[i]);
    }
    red[tid] = acc;
    __syncthreads();
    for (int s = 128; s; s >>= 1) {
        if (tid < s) red[tid] += red[tid + s];
        __syncthreads();
    }
    if (tid == 0)
        out[0] = red[0] + 0.1f * g_sonnet_sum / (float)Bs;
    __syncthreads();
    // reset for next graph replay (all reads above complete)
    for (int i = tid; i < 512; i += 256) { g_S[i] = 0.f; g_pos[i] = 0.f; }
    if (tid == 0) { g_sonnet_sum = 0.f; g_cnt = 0; g_done = 0; }
}

// ---------------- fused main kernel ----------------
// Contrastive blocks FIRST (start at t=0, hide under the MLM stream); MLM segs after.
__global__ void __launch_bounds__(256, 4)
k_main(const float* __restrict__ logits, int V,
       const float* __restrict__ lA, const float* __restrict__ lP,
       const float* __restrict__ lN, int PL, int NL, int LA, int LN,
       const float* __restrict__ qA, const float* __restrict__ qP,
       const float* __restrict__ qN, int PQ, int NQ, int QA, int QN,
       const float* __restrict__ sE, int Bs,
       float* __restrict__ out, float invPL, float invPQ) {
    __shared__ float s_anc[8][DD];   // per-warp anchor slice (contrastive roles)
    int b = blockIdx.x;
    int C1 = LA * LN, C2 = QA * QN;
    if (b < C1) {
        infonce_block(lA, lP, lN, g_invLA, g_invLP, g_invLN, PL, NL,
                      b / LN, b % LN, 0, s_anc[threadIdx.x >> 5]);
    } else if (b < C1 + C2) {
        int bb = b - C1;
        infonce_block(qA, qP, qN, g_invQA, g_invQP, g_invQN, PQ, NQ,
                      bb / QN, bb % QN, PL, s_anc[threadIdx.x >> 5]);
    } else if (b == C1 + C2) {
        sonnet_block(sE, Bs, s_anc[threadIdx.x >> 5]);
    } else {
        mlm_seg(logits, V, b - (C1 + C2 + 1));
    }
    // last-block-done finalization
    __syncthreads();
    __threadfence();
    __shared__ int s_last;
    if (threadIdx.x == 0)
        s_last = (atomicAdd(&g_done, 1) == (int)gridDim.x - 1) ? 1 : 0;
    __syncthreads();
    if (s_last) {
        __threadfence();
        finalize(out, PL, PQ, invPL, invPQ, Bs);
    }
}

extern "C" void kernel_launch(void* const* d_in, const int* in_sizes, int n_in,
                              void* d_out, int out_size) {
    const float* logits = (const float*)d_in[0];
    const void*  labels = d_in[1];
    const float* lA = (const float*)d_in[2];
    const float* lP = (const float*)d_in[3];
    const float* lN = (const float*)d_in[4];
    const float* qA = (const float*)d_in[5];
    const float* qP = (const float*)d_in[6];
    const float* qN = (const float*)d_in[7];
    const float* sE = (const float*)d_in[8];

    int nRows = in_sizes[1];
    int V  = in_sizes[0] / nRows;
    int PL = in_sizes[2] / DD, NL = in_sizes[4] / DD;
    int PQ = in_sizes[5] / DD, NQ = in_sizes[7] / DD;
    int Bs = in_sizes[8] / DD;

    int LA = (PL + 7) / 8,  LN = (NL + 63) / 64;
    int QA = (PQ + 7) / 8,  QN = (NQ + 63) / 64;

    k_init<<<NINIT, 256>>>(labels, nRows, lA, lP, lN, PL, NL,
                           qA, qP, qN, PQ, NQ, sE, Bs);
    int grid = LA * LN + QA * QN + 1 + NMLM;
    k_main<<<grid, 256>>>(logits, V,
                          lA, lP, lN, PL, NL, LA, LN,
                          qA, qP, qN, PQ, NQ, QA, QN,
                          sE, Bs,
                          (float*)d_out, 1.0f / PL, 1.0f / PQ);
}

// round 13
// speedup vs baseline: 2.1542x; 1.2129x over previous
#include <cuda_runtime.h>

#define DD 768
#define Q6 6
#define INV_T 14.285714285714286f
#define CSHIFT 14.285714285714286f
#define MAXROWS 8192
#define NINIT 110
#define NTILE 32
#define NMLMB 640

// ---- persistent device state (zero at load; k_init re-zeroes accumulators each replay,
// ---- finalize resets the counters it owns) ----
static __device__ float g_S[512];
static __device__ float g_pos[512];
static __device__ float g_sonS[32];
static __device__ float g_sonD[32];
static __device__ int   g_rowIdx[MAXROWS];
static __device__ int   g_labArr[MAXROWS];
static __device__ float g_rowS[MAXROWS];
static __device__ float g_labLogit[MAXROWS];
static __device__ int   g_cnt;
static __device__ int   g_done;
static __device__ float g_invLN[256], g_invQN[128];
static __device__ float g_invLA[256], g_invQA[128];
static __device__ float g_invLP[256], g_invQP[128];
static __device__ float g_invSon[32];

__device__ __forceinline__ float wsum(float v) {
    v += __shfl_xor_sync(0xffffffffu, v, 16);
    v += __shfl_xor_sync(0xffffffffu, v, 8);
    v += __shfl_xor_sync(0xffffffffu, v, 4);
    v += __shfl_xor_sync(0xffffffffu, v, 2);
    v += __shfl_xor_sync(0xffffffffu, v, 1);
    return v;
}

__device__ __forceinline__ float sumsq_row(const float* __restrict__ row, int lane) {
    const float4* r4 = (const float4*)row;
    float sq = 0.f;
#pragma unroll
    for (int q = 0; q < Q6; ++q) {
        float4 t = r4[lane + 32 * q];
        sq = fmaf(t.x, t.x, sq); sq = fmaf(t.y, t.y, sq);
        sq = fmaf(t.z, t.z, sq); sq = fmaf(t.w, t.w, sq);
    }
    return sq;
}

// ---------------- k_init: zero accumulators + dtype detect + compact rows + all norms ----------------
__global__ void __launch_bounds__(256) k_init(const void* __restrict__ labels, int nRows,
    const float* __restrict__ lA, const float* __restrict__ lP, const float* __restrict__ lN,
    int PL, int NL,
    const float* __restrict__ qA, const float* __restrict__ qP, const float* __restrict__ qN,
    int PQ, int NQ,
    const float* __restrict__ sE, int Bs)
{
    int tid = threadIdx.x;
    if (blockIdx.x == 0) {      // zero contrastive accumulators (stream-serial w.r.t. k_ctr)
        for (int i = tid; i < 512; i += 256) { g_S[i] = 0.f; g_pos[i] = 0.f; }
        if (tid < 32) g_sonS[tid] = 0.f;
    }
    __shared__ int s_ok;
    if (tid == 0) s_ok = 1;
    __syncthreads();
    // int64 little-endian: odd int32 words are sign extensions (0 or -1).
    const int2* p2 = (const int2*)labels;
    int half = nRows >> 1;
    bool bad = false;
    for (int i = tid; i < half; i += 256) {
        int hi = p2[i].y;
        if (hi != 0 && hi != -1) bad = true;
    }
    if (bad) s_ok = 0;   // benign race: all writers store 0
    __syncthreads();
    int lab64 = s_ok;
    const int* p = (const int*)labels;
    int gtid = blockIdx.x * 256 + tid;
    int gsz  = NINIT * 256;
    for (int r = gtid; r < nRows; r += gsz) {
        int lab = lab64 ? (int)((const long long*)labels)[r] : p[r];
        if (lab >= 0) {
            int slot = atomicAdd(&g_cnt, 1);
            g_rowIdx[slot] = r;
            g_labArr[slot] = lab;
            g_rowS[slot]   = 0.f;
        }
    }
    // inverse norms: one warp per row over the concatenated task list (~880 rows)
    int lane = tid & 31;
    int gw = gtid >> 5;
    int nw = gsz >> 5;
    int e0 = NL, e1 = e0 + NQ, e2 = e1 + PL, e3 = e2 + PQ, e4 = e3 + PL, e5 = e4 + PQ, e6 = e5 + Bs;
    for (int r = gw; r < e6; r += nw) {
        const float* src; float* dst;
        if      (r < e0) { src = lN + (size_t)r * DD;        dst = g_invLN + r; }
        else if (r < e1) { src = qN + (size_t)(r-e0) * DD;   dst = g_invQN + (r-e0); }
        else if (r < e2) { src = lA + (size_t)(r-e1) * DD;   dst = g_invLA + (r-e1); }
        else if (r < e3) { src = qA + (size_t)(r-e2) * DD;   dst = g_invQA + (r-e2); }
        else if (r < e4) { src = lP + (size_t)(r-e3) * DD;   dst = g_invLP + (r-e3); }
        else if (r < e5) { src = qP + (size_t)(r-e4) * DD;   dst = g_invQP + (r-e4); }
        else             { src = sE + (size_t)(r-e5) * DD;   dst = g_invSon + (r-e5); }
        float sq = wsum(sumsq_row(src, lane));
        if (lane == 0) *dst = rsqrtf(fmaxf(sq, 1e-24f));
    }
}

// ------- InfoNCE tile: 8 anchors x <=NTILE negatives, anchor staged in SMEM -------
__device__ void infonce_block(const float* __restrict__ A,
                              const float* __restrict__ Pp,
                              const float* __restrict__ Ng,
                              const float* __restrict__ invA,
                              const float* __restrict__ invP,
                              const float* __restrict__ invN,
                              int nP, int nN, int ga, int gn, int Sbase,
                              float* __restrict__ s_anc) {
    int tid = threadIdx.x, w = tid >> 5, lane = tid & 31;
    int nBase = gn * NTILE;
    int nCnt = min(NTILE, nN - nBase);
    int a = ga * 8 + w;
    if (a >= nP) return;
    float scale = invA[a] * INV_T;
    {   // scaled anchor -> this warp's smem slice
        const float4* ar = (const float4*)(A + (size_t)a * DD);
        float4* sa = (float4*)s_anc;
#pragma unroll
        for (int q = 0; q < Q6; ++q) {
            float4 t = ar[lane + 32 * q];
            t.x *= scale; t.y *= scale; t.z *= scale; t.w *= scale;
            sa[lane + 32 * q] = t;
        }
    }
    __syncwarp();
    const float4* sa = (const float4*)s_anc;

    float acc = 0.f;
    int j = 0;
    for (; j + 4 <= nCnt; j += 4) {
        const float4* r0 = (const float4*)(Ng + (size_t)(nBase + j + 0) * DD);
        const float4* r1 = (const float4*)(Ng + (size_t)(nBase + j + 1) * DD);
        const float4* r2 = (const float4*)(Ng + (size_t)(nBase + j + 2) * DD);
        const float4* r3 = (const float4*)(Ng + (size_t)(nBase + j + 3) * DD);
        float d0 = 0.f, d1 = 0.f, d2 = 0.f, d3 = 0.f;
#pragma unroll
        for (int q = 0; q < Q6; ++q) {
            int ix = lane + 32 * q;
            float4 av = sa[ix];
            float4 t0 = r0[ix], t1 = r1[ix], t2 = r2[ix], t3 = r3[ix];
            d0 = fmaf(av.x, t0.x, d0); d0 = fmaf(av.y, t0.y, d0);
            d0 = fmaf(av.z, t0.z, d0); d0 = fmaf(av.w, t0.w, d0);
            d1 = fmaf(av.x, t1.x, d1); d1 = fmaf(av.y, t1.y, d1);
            d1 = fmaf(av.z, t1.z, d1); d1 = fmaf(av.w, t1.w, d1);
            d2 = fmaf(av.x, t2.x, d2); d2 = fmaf(av.y, t2.y, d2);
            d2 = fmaf(av.z, t2.z, d2); d2 = fmaf(av.w, t2.w, d2);
            d3 = fmaf(av.x, t3.x, d3); d3 = fmaf(av.y, t3.y, d3);
            d3 = fmaf(av.z, t3.z, d3); d3 = fmaf(av.w, t3.w, d3);
        }
        d0 = wsum(d0); d1 = wsum(d1); d2 = wsum(d2); d3 = wsum(d3);
        acc += __expf(fmaf(d0, invN[nBase + j + 0], -CSHIFT));
        acc += __expf(fmaf(d1, invN[nBase + j + 1], -CSHIFT));
        acc += __expf(fmaf(d2, invN[nBase + j + 2], -CSHIFT));
        acc += __expf(fmaf(d3, invN[nBase + j + 3], -CSHIFT));
    }
    for (; j < nCnt; ++j) {
        const float4* r4 = (const float4*)(Ng + (size_t)(nBase + j) * DD);
        float d = 0.f;
#pragma unroll
        for (int q = 0; q < Q6; ++q) {
            int ix = lane + 32 * q;
            float4 av = sa[ix];
            float4 t = r4[ix];
            d = fmaf(av.x, t.x, d); d = fmaf(av.y, t.y, d);
            d = fmaf(av.z, t.z, d); d = fmaf(av.w, t.w, d);
        }
        d = wsum(d);
        acc += __expf(fmaf(d, invN[nBase + j], -CSHIFT));
    }
    if (gn == 0) {
        const float4* r4 = (const float4*)(Pp + (size_t)a * DD);
        float dp = 0.f;
#pragma unroll
        for (int q = 0; q < Q6; ++q) {
            int ix = lane + 32 * q;
            float4 av = sa[ix];
            float4 t = r4[ix];
            dp = fmaf(av.x, t.x, dp); dp = fmaf(av.y, t.y, dp);
            dp = fmaf(av.z, t.z, dp); dp = fmaf(av.w, t.w, dp);
        }
        dp = wsum(dp);
        float pos = dp * invP[a];
        acc += __expf(pos - CSHIFT);
        if (lane == 0) g_pos[Sbase + a] = pos;
    }
    if (lane == 0) atomicAdd(&g_S[Sbase + a], acc);
}

// ---- sonnet: 4 rows per block, 2 warps per row (j split in halves), logs deferred ----
__device__ void sonnet_block(const float* __restrict__ E, int Bs, int sb,
                             float* __restrict__ s_anc) {
    int tid = threadIdx.x, w = tid >> 5, lane = tid & 31;
    int r = sb * 4 + (w >> 1);
    if (r >= Bs) return;
    int par = w & 1;
    int jh = (Bs + 1) >> 1;
    int jb = par ? jh : 0;
    int je = par ? Bs : jh;
    float s = g_invSon[r] * INV_T;
    {
        const float4* ar = (const float4*)(E + (size_t)r * DD);
        float4* sa = (float4*)s_anc;
#pragma unroll
        for (int q = 0; q < Q6; ++q) {
            float4 t = ar[lane + 32 * q];
            t.x *= s; t.y *= s; t.z *= s; t.w *= s;
            sa[lane + 32 * q] = t;
        }
    }
    __syncwarp();
    const float4* sa = (const float4*)s_anc;
    float acc = 0.f;
    for (int j = jb; j < je; ++j) {
        const float4* r4 = (const float4*)(E + (size_t)j * DD);
        float d = 0.f;
#pragma unroll
        for (int q = 0; q < Q6; ++q) {
            int ix = lane + 32 * q;
            float4 av = sa[ix];
            float4 t = r4[ix];
            d = fmaf(av.x, t.x, d); d = fmaf(av.y, t.y, d);
            d = fmaf(av.z, t.z, d); d = fmaf(av.w, t.w, d);
        }
        d = wsum(d);
        float sim = d * g_invSon[j];
        acc += __expf(sim - CSHIFT);
        if (j == r && lane == 0) g_sonD[r] = sim;   // single writer
    }
    if (lane == 0) atomicAdd(&g_sonS[r], acc);
}

// ---------------- k_ctr: all contrastive work ----------------
__global__ void __launch_bounds__(256)
k_ctr(const float* __restrict__ lA, const float* __restrict__ lP,
      const float* __restrict__ lN, int PL, int NL, int LA, int LN,
      const float* __restrict__ qA, const float* __restrict__ qP,
      const float* __restrict__ qN, int PQ, int NQ, int QA, int QN,
      const float* __restrict__ sE, int Bs) {
    __shared__ float s_anc[8][DD];
    int b = blockIdx.x;
    int C1 = LA * LN, C2 = QA * QN;
    if (b < C1) {
        infonce_block(lA, lP, lN, g_invLA, g_invLP, g_invLN, PL, NL,
                      b / LN, b % LN, 0, s_anc[threadIdx.x >> 5]);
    } else if (b < C1 + C2) {
        int bb = b - C1;
        infonce_block(qA, qP, qN, g_invQA, g_invQP, g_invQN, PQ, NQ,
                      bb / QN, bb % QN, PL, s_anc[threadIdx.x >> 5]);
    } else {
        sonnet_block(sE, Bs, b - (C1 + C2), s_anc[threadIdx.x >> 5]);
    }
}

// ---------------- finalize (last k_mlm block) ----------------
__device__ void finalize(float* __restrict__ out, int PL, int PQ,
                         float invPL, float invPQ, int Bs) {
    __shared__ float red[256];
    int tid = threadIdx.x;
    int nv = g_cnt;
    float acc = 0.f;
    for (int i = tid; i < nv; i += 256)
        acc += logf(g_rowS[i]) - g_labLogit[i];
    acc *= 0.5f / (float)max(nv, 1);
    for (int i = tid; i < PL + PQ; i += 256) {
        float wgt = (i < PL) ? (0.2f * invPL) : (0.2f * invPQ);
        acc += wgt * (logf(g_S[i]) + CSHIFT - g_pos[i]);
    }
    for (int i = tid; i < Bs; i += 256)
        acc += (0.1f / (float)Bs) * (logf(g_sonS[i]) + CSHIFT - g_sonD[i]);
    red[tid] = acc;
    __syncthreads();
    for (int s = 128; s; s >>= 1) {
        if (tid < s) red[tid] += red[tid + s];
        __syncthreads();
    }
    if (tid == 0) {
        out[0] = red[0];
        g_cnt = 0; g_done = 0;       // counters for next replay
    }
}

// ---------------- k_mlm: one full row per block, grid-stride ----------------
__global__ void __launch_bounds__(256)
k_mlm(const float* __restrict__ logits, int V,
      float* __restrict__ out, int PL, int PQ,
      float invPL, float invPQ, int Bs) {
    int cnt = g_cnt;
    const float4* __restrict__ x4 = (const float4*)logits;   // base 256B-aligned
    for (int slot = blockIdx.x; slot < cnt; slot += gridDim.x) {
        int row = g_rowIdx[slot];
        long long e0 = (long long)row * V;
        long long e1 = e0 + V;
        int f0 = (int)((e0 + 3) >> 2);   // first full float4
        int f1 = (int)(e1 >> 2);         // end float4 (exclusive)
        float a0 = 0.f, a1 = 0.f, a2 = 0.f, a3 = 0.f;
        if (threadIdx.x == 0) {          // scalar head/tail (<=3 each) + label logit
            long long hE = ((long long)f0) << 2;
            for (long long e = e0; e < hE; ++e) a0 += __expf(logits[e]);
            long long tB = ((long long)f1) << 2;
            for (long long e = tB; e < e1; ++e) a1 += __expf(logits[e]);
            g_labLogit[slot] = logits[e0 + g_labArr[slot]];
        }
#define CONS(v) { a0 += __expf(v.x); a1 += __expf(v.y); a2 += __expf(v.z); a3 += __expf(v.w); }
        int nfull = (f1 - f0) >> 10;     // full 1024-float4 batches (~3 per row)
        int base = f0 + threadIdx.x;
        if (nfull > 0) {                 // guard-free pipelined main stream
            float4 va0 = x4[base], va1 = x4[base + 256],
                   va2 = x4[base + 512], va3 = x4[base + 768];
            for (int bb = 1; bb < nfull; ++bb) {
                int ib = base + (bb << 10);
                float4 vb0 = x4[ib], vb1 = x4[ib + 256],
                       vb2 = x4[ib + 512], vb3 = x4[ib + 768];
                CONS(va0); CONS(va1); CONS(va2); CONS(va3);
                va0 = vb0; va1 = vb1; va2 = vb2; va3 = vb3;
            }
            CONS(va0); CONS(va1); CONS(va2); CONS(va3);
            base += nfull << 10;
        }
        {   // epilogue: < 1024 float4s, guarded
            if (base < f1)       { float4 v = x4[base];       CONS(v); }
            if (base + 256 < f1) { float4 v = x4[base + 256]; CONS(v); }
            if (base + 512 < f1) { float4 v = x4[base + 512]; CONS(v); }
            if (base + 768 < f1) { float4 v = x4[base + 768]; CONS(v); }
        }
#undef CONS
        float wv = wsum(a0 + a1 + a2 + a3);
        if ((threadIdx.x & 31) == 0) atomicAdd(&g_rowS[slot], wv);
    }
    // last-block-done finalization
    __syncthreads();
    __threadfence();
    __shared__ int s_last;
    if (threadIdx.x == 0)
        s_last = (atomicAdd(&g_done, 1) == (int)gridDim.x - 1) ? 1 : 0;
    __syncthreads();
    if (s_last) {
        __threadfence();
        finalize(out, PL, PQ, invPL, invPQ, Bs);
    }
}

extern "C" void kernel_launch(void* const* d_in, const int* in_sizes, int n_in,
                              void* d_out, int out_size) {
    const float* logits = (const float*)d_in[0];
    const void*  labels = d_in[1];
    const float* lA = (const float*)d_in[2];
    const float* lP = (const float*)d_in[3];
    const float* lN = (const float*)d_in[4];
    const float* qA = (const float*)d_in[5];
    const float* qP = (const float*)d_in[6];
    const float* qN = (const float*)d_in[7];
    const float* sE = (const float*)d_in[8];

    int nRows = in_sizes[1];
    int V  = in_sizes[0] / nRows;
    int PL = in_sizes[2] / DD, NL = in_sizes[4] / DD;
    int PQ = in_sizes[5] / DD, NQ = in_sizes[7] / DD;
    int Bs = in_sizes[8] / DD;

    int LA = (PL + 7) / 8,  LN = (NL + NTILE - 1) / NTILE;
    int QA = (PQ + 7) / 8,  QN = (NQ + NTILE - 1) / NTILE;
    int SB = (Bs + 3) / 4;

    k_init<<<NINIT, 256>>>(labels, nRows, lA, lP, lN, PL, NL,
                           qA, qP, qN, PQ, NQ, sE, Bs);
    k_ctr<<<LA * LN + QA * QN + SB, 256>>>(lA, lP, lN, PL, NL, LA, LN,
                                           qA, qP, qN, PQ, NQ, QA, QN, sE, Bs);
    k_mlm<<<NMLMB, 256>>>(logits, V, (float*)d_out, PL, PQ,
                          1.0f / PL, 1.0f / PQ, Bs);
}